// round 15
// baseline (speedup 1.0000x reference)
#include <cuda_runtime.h>
#include <cuda_bf16.h>
#include <math.h>
#include <float.h>
#include <stdint.h>

// Problem constants
#define BB   2
#define DD   512
#define NN   2048
#define HH   8
#define DD2  1024
#define EPSV 1e-5f
#define SCALE2 0.1803368801111244f   // 0.125 * log2(e)

// ---------------------------------------------------------------------------
// Scratch
// ---------------------------------------------------------------------------
__device__ uint2 g_qp[BB * HH * 32 * NN];    // attention Q [b,h][dkp][n]  (hi,lo) pairs along dk
__device__ uint2 g_kp[BB * HH * 32 * NN];    // attention K
__device__ uint2 g_vp[BB * HH * 1024 * 64];  // attention V [b,h][np][dk]  pairs along n
__device__ float g_x [BB * DD  * NN];
__device__ float g_xm[BB * DD  * NN];
__device__ float g_h [BB * DD2 * NN];
__device__ unsigned long long g_mbits[BB * NN * 32];  // 1 MB bitmask

// ---------------------------------------------------------------------------
// Helpers
// ---------------------------------------------------------------------------
__device__ __forceinline__ uint32_t pk2(float lo, float hi) {
    uint32_t r;
    asm("cvt.rn.bf16x2.f32 %0, %1, %2;" : "=r"(r) : "f"(hi), "f"(lo));
    return r;
}
__device__ __forceinline__ float bf16val(float x) {
    return __bfloat162float(__float2bfloat16_rn(x));
}
__device__ __forceinline__ void mma16816(float c[4], const uint32_t a[4], const uint32_t b[2]) {
    asm volatile(
        "mma.sync.aligned.m16n8k16.row.col.f32.bf16.bf16.f32 "
        "{%0,%1,%2,%3}, {%4,%5,%6,%7}, {%8,%9}, {%0,%1,%2,%3};"
        : "+f"(c[0]), "+f"(c[1]), "+f"(c[2]), "+f"(c[3])
        : "r"(a[0]), "r"(a[1]), "r"(a[2]), "r"(a[3]), "r"(b[0]), "r"(b[1]));
}
#define CPA(sm, gm) asm volatile("cp.async.cg.shared.global [%0], [%1], 16;" :: "r"(sm), "l"(gm))
__device__ __forceinline__ uint32_t smaddr(const void* p) {
    return (uint32_t)__cvta_generic_to_shared(p);
}

// ---------------------------------------------------------------------------
// Mask -> bitmask (split into 2 launches for ncu positioning)
// ---------------------------------------------------------------------------
__global__ void maskbits_kernel(const int* __restrict__ mask, int base)
{
    const int idx = base + blockIdx.x * 256 + threadIdx.x;  // half of BB*NN*32
    const int b = idx >> 16;
    const int r = (idx >> 5) & (NN - 1);
    const int w = idx & 31;
    const int4* mp = (const int4*)(mask + ((size_t)b * NN + r) * NN + w * 64);
    unsigned long long bits = 0ULL;
#pragma unroll
    for (int i = 0; i < 16; ++i) {
        const int4 m4 = mp[i];
        bits |= (unsigned long long)(m4.x != 0) << (4 * i + 0);
        bits |= (unsigned long long)(m4.y != 0) << (4 * i + 1);
        bits |= (unsigned long long)(m4.z != 0) << (4 * i + 2);
        bits |= (unsigned long long)(m4.w != 0) << (4 * i + 3);
    }
    g_mbits[idx] = bits;
}

// ---------------------------------------------------------------------------
// Tensor-core GEMM (R11 config, measured best): CTA 128x128, k-step 32,
// 256 threads, 8 warps (2m x 4n). 2-stage double buffer + reg prefetch.
// 3xBF16 split. MODE 0: fp32+bias. 1: concat+BN+ReLU. 2: packed Q/K epilogue.
// 3: packed V epilogue.
// ---------------------------------------------------------------------------
#define GW_STAGE 9344
#define GEMM_SMEM (2 * GW_STAGE * 4)

template <int MODE>
__device__ __forceinline__ void gemm_body_tc(
    const float* __restrict__ W, const float* __restrict__ X,
    const float* __restrict__ X2, const float* __restrict__ bias,
    const float* __restrict__ rmean, const float* __restrict__ rvar,
    const float* __restrict__ gam,   const float* __restrict__ bet,
    void* __restrict__ outv, int O, int I)
{
    extern __shared__ uint32_t gsm[];

    const int tid  = threadIdx.x;
    const int lane = tid & 31, warp = tid >> 5;
    const int g = lane >> 2, tg = lane & 3;
    const int n0 = blockIdx.x * 128, o0 = blockIdx.y * 128;
    const int wm = (warp >> 2) * 64;
    const int wn = (warp & 3) * 32;

    float acc[4][4][4];
#pragma unroll
    for (int mi = 0; mi < 4; ++mi)
#pragma unroll
        for (int ni = 0; ni < 4; ++ni)
#pragma unroll
            for (int t = 0; t < 4; ++t) acc[mi][ni][t] = 0.f;

    float4 pa[4], pbx0[2], pbx1[2];

#define G_LDG(K0) do {                                                         \
    _Pragma("unroll")                                                          \
    for (int s = 0; s < 4; ++s) {                                              \
        const int u = tid + s * 256;                                           \
        const int o = u >> 3;                                                  \
        const int kc = (u & 7) << 2;                                           \
        pa[s] = *(const float4*)(W + (size_t)(o0 + o) * I + (K0) + kc);        \
    }                                                                          \
    _Pragma("unroll")                                                          \
    for (int s = 0; s < 2; ++s) {                                              \
        const int u = tid + s * 256;                                           \
        const int kp = u >> 5;                                                 \
        const int nc = (u & 31) << 2;                                          \
        const int row0 = (K0) + kp * 2;                                        \
        const float *s0p, *s1p;                                                \
        if (MODE == 1) {                                                       \
            s0p = (row0 < DD) ? (X + (size_t)row0 * NN)                        \
                              : (X2 + (size_t)(row0 - DD) * NN);               \
            const int row1 = row0 + 1;                                         \
            s1p = (row1 < DD) ? (X + (size_t)row1 * NN)                        \
                              : (X2 + (size_t)(row1 - DD) * NN);               \
        } else {                                                               \
            s0p = X + (size_t)row0 * NN;                                       \
            s1p = s0p + NN;                                                    \
        }                                                                      \
        pbx0[s] = *(const float4*)(s0p + n0 + nc);                             \
        pbx1[s] = *(const float4*)(s1p + n0 + nc);                             \
    } } while (0)

#define G_STS(ST) do {                                                         \
    uint32_t* AHp = gsm + (ST) * GW_STAGE;                                     \
    uint32_t* ALp = AHp + 2560;                                                \
    uint32_t* BHp = AHp + 5120;                                                \
    uint32_t* BLp = AHp + 7232;                                                \
    _Pragma("unroll")                                                          \
    for (int s = 0; s < 4; ++s) {                                              \
        const int u = tid + s * 256;                                           \
        const int o = u >> 3;                                                  \
        const int kc = (u & 7) << 2;                                           \
        const float4 w4 = pa[s];                                               \
        const float hx = bf16val(w4.x), hy = bf16val(w4.y);                    \
        const float hz = bf16val(w4.z), hw = bf16val(w4.w);                    \
        *(uint2*)&AHp[o * 20 + (kc >> 1)] = make_uint2(pk2(hx, hy), pk2(hz, hw)); \
        *(uint2*)&ALp[o * 20 + (kc >> 1)] =                                    \
            make_uint2(pk2(w4.x - hx, w4.y - hy), pk2(w4.z - hz, w4.w - hw));  \
    }                                                                          \
    _Pragma("unroll")                                                          \
    for (int s = 0; s < 2; ++s) {                                              \
        const int u = tid + s * 256;                                           \
        const int kp = u >> 5;                                                 \
        const int nc = (u & 31) << 2;                                          \
        const float4 x0 = pbx0[s], x1 = pbx1[s];                               \
        const float h0x = bf16val(x0.x), h0y = bf16val(x0.y),                  \
                    h0z = bf16val(x0.z), h0w = bf16val(x0.w);                  \
        const float h1x = bf16val(x1.x), h1y = bf16val(x1.y),                  \
                    h1z = bf16val(x1.z), h1w = bf16val(x1.w);                  \
        uint4 hv, lv;                                                          \
        hv.x = pk2(h0x, h1x); hv.y = pk2(h0y, h1y);                            \
        hv.z = pk2(h0z, h1z); hv.w = pk2(h0w, h1w);                            \
        lv.x = pk2(x0.x - h0x, x1.x - h1x); lv.y = pk2(x0.y - h0y, x1.y - h1y);\
        lv.z = pk2(x0.z - h0z, x1.z - h1z); lv.w = pk2(x0.w - h0w, x1.w - h1w);\
        *(uint4*)&BHp[kp * 132 + nc] = hv;                                     \
        *(uint4*)&BLp[kp * 132 + nc] = lv;                                     \
    } } while (0)

    const int T = I / 32;
    G_LDG(0);
    G_STS(0);
    G_LDG(32);
    __syncthreads();

    for (int t = 0; t < T; ++t) {
        const uint32_t* AHp = gsm + (t & 1) * GW_STAGE;
        const uint32_t* ALp = AHp + 2560;
        const uint32_t* BHp = AHp + 5120;
        const uint32_t* BLp = AHp + 7232;
#pragma unroll
        for (int ks = 0; ks < 2; ++ks) {
            const int kb = ks * 8;
            uint32_t ah[4][4], al[4][4];
#pragma unroll
            for (int mi = 0; mi < 4; ++mi) {
                const int r0 = wm + mi * 16 + g;
                ah[mi][0] = AHp[r0 * 20 + kb + tg];
                ah[mi][1] = AHp[(r0 + 8) * 20 + kb + tg];
                ah[mi][2] = AHp[r0 * 20 + kb + tg + 4];
                ah[mi][3] = AHp[(r0 + 8) * 20 + kb + tg + 4];
                al[mi][0] = ALp[r0 * 20 + kb + tg];
                al[mi][1] = ALp[(r0 + 8) * 20 + kb + tg];
                al[mi][2] = ALp[r0 * 20 + kb + tg + 4];
                al[mi][3] = ALp[(r0 + 8) * 20 + kb + tg + 4];
            }
#pragma unroll
            for (int ni = 0; ni < 4; ++ni) {
                const int c0 = wn + ni * 8 + g;
                uint32_t bh[2] = { BHp[(kb + tg) * 132 + c0], BHp[(kb + tg + 4) * 132 + c0] };
                uint32_t bl[2] = { BLp[(kb + tg) * 132 + c0], BLp[(kb + tg + 4) * 132 + c0] };
#pragma unroll
                for (int mi = 0; mi < 4; ++mi) {
                    mma16816(acc[mi][ni], ah[mi], bh);
                    mma16816(acc[mi][ni], ah[mi], bl);
                    mma16816(acc[mi][ni], al[mi], bh);
                }
            }
        }
        if (t + 1 < T) {
            G_STS((t + 1) & 1);
            if (t + 2 < T) G_LDG((t + 2) * 32);
        }
        __syncthreads();
    }
#undef G_LDG
#undef G_STS

    // --- epilogues ---
    if (MODE <= 1) {
        float* out = (float*)outv;
#pragma unroll
        for (int mi = 0; mi < 4; ++mi) {
#pragma unroll
            for (int rr = 0; rr < 2; ++rr) {
                const int o = o0 + wm + mi * 16 + rr * 8 + g;
                const float bi = bias[o];
                float sc = 1.f, sh = bi;
                if (MODE == 1) {
                    const float s = gam[o] * rsqrtf(rvar[o] + EPSV);
                    sc = s;
                    sh = (bi - rmean[o]) * s + bet[o];
                }
#pragma unroll
                for (int ni = 0; ni < 4; ++ni) {
                    float v0 = acc[mi][ni][rr * 2 + 0] * sc + sh;
                    float v1 = acc[mi][ni][rr * 2 + 1] * sc + sh;
                    if (MODE == 1) { v0 = fmaxf(v0, 0.f); v1 = fmaxf(v1, 0.f); }
                    *(float2*)(out + (size_t)o * NN + n0 + wn + ni * 8 + tg * 2) =
                        make_float2(v0, v1);
                }
            }
        }
    } else if (MODE == 2) {
        // Q/K pack: pairs along dk (channels o_e and o_e+8 -> dk, dk+1, same h).
        uint2* outp = (uint2*)outv;
#pragma unroll
        for (int mi = 0; mi < 4; ++mi) {
            const int o_e = o0 + wm + mi * 16 + g;       // o_e & 8 == 0
            const float be = bias[o_e], bo = bias[o_e + 8];
            const int hh = o_e & 7, dkp = o_e >> 4;
            uint2* rowp = outp + ((size_t)hh * 32 + dkp) * NN;
#pragma unroll
            for (int ni = 0; ni < 4; ++ni) {
                const float v00 = acc[mi][ni][0] + be, v01 = acc[mi][ni][1] + be;
                const float v10 = acc[mi][ni][2] + bo, v11 = acc[mi][ni][3] + bo;
                const float h00 = bf16val(v00), h01 = bf16val(v01);
                const float h10 = bf16val(v10), h11 = bf16val(v11);
                uint4 pv;
                pv.x = pk2(h00, h10); pv.y = pk2(v00 - h00, v10 - h10);
                pv.z = pk2(h01, h11); pv.w = pk2(v01 - h01, v11 - h11);
                *(uint4*)(rowp + n0 + wn + ni * 8 + tg * 2) = pv;
            }
        }
    } else {
        // V pack: pairs along n. Layout [h][np][dk].
        uint2* outp = (uint2*)outv;
#pragma unroll
        for (int mi = 0; mi < 4; ++mi) {
#pragma unroll
            for (int rr = 0; rr < 2; ++rr) {
                const int o = o0 + wm + mi * 16 + rr * 8 + g;
                const float bo = bias[o];
                const int hh = o & 7, dk = o >> 3;
                uint2* colp = outp + (size_t)hh * 1024 * 64 + dk;
#pragma unroll
                for (int ni = 0; ni < 4; ++ni) {
                    const float va = acc[mi][ni][rr * 2 + 0] + bo;
                    const float vb = acc[mi][ni][rr * 2 + 1] + bo;
                    const float ha = bf16val(va), hb2 = bf16val(vb);
                    uint2 val;
                    val.x = pk2(ha, hb2);
                    val.y = pk2(va - ha, vb - hb2);
                    const int np = (n0 + wn + ni * 8 + tg * 2) >> 1;
                    colp[(size_t)np * 64] = val;
                }
            }
        }
    }
}

// Separate projection kernels (also positions attention as launch #6 for ncu)
template <int MODE>
__global__ __launch_bounds__(256)
void proj_kernel(const float* __restrict__ X, const float* __restrict__ W,
                 const float* __restrict__ bias, uint2* __restrict__ outp)
{
    const int b = blockIdx.z;
    gemm_body_tc<MODE>(W, X + (size_t)b * DD * NN, nullptr, bias,
                       nullptr, nullptr, nullptr, nullptr,
                       (void*)(outp + (size_t)b * 524288), DD, DD);
}

template <int MODE>
__global__ __launch_bounds__(256)
void gemm_kernel(const float* __restrict__ W, const float* __restrict__ X,
                 const float* __restrict__ X2, const float* __restrict__ bias,
                 const float* __restrict__ rmean, const float* __restrict__ rvar,
                 const float* __restrict__ gam,   const float* __restrict__ bet,
                 float* __restrict__ out, int O, int I)
{
    const int b = blockIdx.z;
    const size_t xs = (MODE == 1) ? (size_t)DD * NN : (size_t)I * NN;
    gemm_body_tc<MODE>(W, X + (size_t)b * xs,
                       (MODE == 1) ? (X2 + (size_t)b * DD * NN) : nullptr,
                       bias, rmean, rvar, gam, bet,
                       (void*)(out + (size_t)b * O * NN), O, I);
}

// ---------------------------------------------------------------------------
// Flash attention v3: 64-col K tiles, 2-stage cp.async K/V pipeline, Q frags
// in registers, exp2-domain softmax. CTA: 64 q-rows x (b,h), 128 threads.
// Stage (uint2): K[32][68]=2176 | V[32][68]=2176 -> 4352. 2 stages = 69632 B.
// 3 CTAs/SM target.
// ---------------------------------------------------------------------------
#define ATS 4352
#define ATT_SMEM (2 * ATS * 8)   // 69632 B

__global__ __launch_bounds__(128, 3)
void attn_tc_kernel()
{
    extern __shared__ uint2 smu2[];

    const int tid  = threadIdx.x;
    const int lane = tid & 31, warp = tid >> 5;
    const int g = lane >> 2, tg = lane & 3;
    const int b = blockIdx.z, h = blockIdx.y, n0 = blockIdx.x * 64;
    const int rb = warp * 16;

    const uint2* qbase = g_qp + ((size_t)(b * HH + h) * 32) * NN;
    const uint2* kbase = g_kp + ((size_t)(b * HH + h) * 32) * NN;
    const uint2* vbase = g_vp + ((size_t)(b * HH + h) * 1024) * 64;

    // --- stage Q [32 dkp][64 r] (stride 68), pull frags to registers ---
    uint32_t qh[4][4], ql[4][4];
    {
        uint2* Qs = smu2;
        const int row = tid >> 2;          // 0..31
        const int c16 = (tid & 3) * 16;    // 0,16,32,48
#pragma unroll
        for (int j = 0; j < 8; ++j)
            *(uint4*)&Qs[row * 68 + c16 + 2 * j] =
                *(const uint4*)(qbase + (size_t)row * NN + n0 + c16 + 2 * j);
        __syncthreads();
        const int r0 = rb + g;
#pragma unroll
        for (int ks = 0; ks < 4; ++ks) {
            const int kb = ks * 8;
            const uint2 q0 = Qs[(kb + tg) * 68 + r0];
            const uint2 q1 = Qs[(kb + tg) * 68 + r0 + 8];
            const uint2 q2 = Qs[(kb + tg + 4) * 68 + r0];
            const uint2 q3 = Qs[(kb + tg + 4) * 68 + r0 + 8];
            qh[ks][0] = q0.x; qh[ks][1] = q1.x; qh[ks][2] = q2.x; qh[ks][3] = q3.x;
            ql[ks][0] = q0.y; ql[ks][1] = q1.y; ql[ks][2] = q2.y; ql[ks][3] = q3.y;
        }
        __syncthreads();
    }

    float oacc[8][4];
#pragma unroll
    for (int ni = 0; ni < 8; ++ni)
#pragma unroll
        for (int t = 0; t < 4; ++t) oacc[ni][t] = 0.f;
    float mrow0 = -INFINITY, mrow8 = -INFINITY, lsum0 = 0.f, lsum8 = 0.f;

    const size_t mrowbase0 = ((size_t)b * NN + n0 + rb + g) * 32;
    const size_t mrowbase8 = mrowbase0 + 8 * 32;

    // cp.async loader: row = tid>>2 (0..31), colbase = (tid&3)*16 (u2)
    const int lrow = tid >> 2;
    const int lcb  = (tid & 3) * 16;

#define AT_LOAD(ST, TT) do {                                                   \
    uint2* Kst = smu2 + (ST) * ATS;                                            \
    uint2* Vst = Kst + 2176;                                                   \
    const int m0_ = (TT) * 64;                                                 \
    const uint2* kg = kbase + (size_t)lrow * NN + m0_ + lcb;                   \
    const uint32_t ks_ = smaddr(Kst + lrow * 68 + lcb);                        \
    CPA(ks_,      kg);     CPA(ks_ + 16, kg + 2);                              \
    CPA(ks_ + 32, kg + 4); CPA(ks_ + 48, kg + 6);                              \
    CPA(ks_ + 64, kg + 8); CPA(ks_ + 80, kg + 10);                             \
    CPA(ks_ + 96, kg + 12); CPA(ks_ + 112, kg + 14);                           \
    const uint2* vg = vbase + (size_t)((m0_ >> 1) + lrow) * 64 + lcb;          \
    const uint32_t vs_ = smaddr(Vst + lrow * 68 + lcb);                        \
    CPA(vs_,      vg);     CPA(vs_ + 16, vg + 2);                              \
    CPA(vs_ + 32, vg + 4); CPA(vs_ + 48, vg + 6);                              \
    CPA(vs_ + 64, vg + 8); CPA(vs_ + 80, vg + 10);                             \
    CPA(vs_ + 96, vg + 12); CPA(vs_ + 112, vg + 14);                           \
    asm volatile("cp.async.commit_group;");                                    \
} while (0)

    AT_LOAD(0, 0);
    AT_LOAD(1, 1);

    const int TTOT = NN / 64;   // 32 tiles
    for (int t = 0; t < TTOT; ++t) {
        asm volatile("cp.async.wait_group 1;");
        __syncthreads();
        const uint2* Kp = smu2 + (t & 1) * ATS;
        const uint2* Vp = Kp + 2176;

        // --- S = Q K^T (3x split) ---
        float sv[8][4];
#pragma unroll
        for (int ni = 0; ni < 8; ++ni)
#pragma unroll
            for (int tt = 0; tt < 4; ++tt) sv[ni][tt] = 0.f;
#pragma unroll
        for (int ks = 0; ks < 4; ++ks) {
            const int kb = ks * 8;
#pragma unroll
            for (int ni = 0; ni < 8; ++ni) {
                const int c0 = ni * 8 + g;
                const uint2 k0 = Kp[(kb + tg) * 68 + c0];
                const uint2 k1 = Kp[(kb + tg + 4) * 68 + c0];
                uint32_t bh[2] = { k0.x, k1.x };
                uint32_t bl[2] = { k0.y, k1.y };
                mma16816(sv[ni], qh[ks], bh);
                mma16816(sv[ni], qh[ks], bl);
                mma16816(sv[ni], ql[ks], bh);
            }
        }

        // --- mask + scale into exp2 domain ---
        const unsigned long long w0 = g_mbits[mrowbase0 + t];
        const unsigned long long w8 = g_mbits[mrowbase8 + t];
#pragma unroll
        for (int ni = 0; ni < 8; ++ni) {
            const int cb = ni * 8 + tg * 2;
            sv[ni][0] = ((w0 >> cb) & 1ULL)       ? sv[ni][0] * SCALE2 : -1e9f;
            sv[ni][1] = ((w0 >> (cb + 1)) & 1ULL) ? sv[ni][1] * SCALE2 : -1e9f;
            sv[ni][2] = ((w8 >> cb) & 1ULL)       ? sv[ni][2] * SCALE2 : -1e9f;
            sv[ni][3] = ((w8 >> (cb + 1)) & 1ULL) ? sv[ni][3] * SCALE2 : -1e9f;
        }

        // --- online softmax (exp2 domain) ---
        float mx0 = -INFINITY, mx8 = -INFINITY;
#pragma unroll
        for (int ni = 0; ni < 8; ++ni) {
            mx0 = fmaxf(mx0, fmaxf(sv[ni][0], sv[ni][1]));
            mx8 = fmaxf(mx8, fmaxf(sv[ni][2], sv[ni][3]));
        }
        mx0 = fmaxf(mx0, __shfl_xor_sync(0xffffffffu, mx0, 1));
        mx0 = fmaxf(mx0, __shfl_xor_sync(0xffffffffu, mx0, 2));
        mx8 = fmaxf(mx8, __shfl_xor_sync(0xffffffffu, mx8, 1));
        mx8 = fmaxf(mx8, __shfl_xor_sync(0xffffffffu, mx8, 2));
        const float mn0 = fmaxf(mrow0, mx0), mn8 = fmaxf(mrow8, mx8);
        const float al0 = exp2f(mrow0 - mn0), al8 = exp2f(mrow8 - mn8);
        mrow0 = mn0; mrow8 = mn8;
        float sum0 = 0.f, sum8 = 0.f;
#pragma unroll
        for (int ni = 0; ni < 8; ++ni) {
            sv[ni][0] = exp2f(sv[ni][0] - mn0); sum0 += sv[ni][0];
            sv[ni][1] = exp2f(sv[ni][1] - mn0); sum0 += sv[ni][1];
            sv[ni][2] = exp2f(sv[ni][2] - mn8); sum8 += sv[ni][2];
            sv[ni][3] = exp2f(sv[ni][3] - mn8); sum8 += sv[ni][3];
        }
        sum0 += __shfl_xor_sync(0xffffffffu, sum0, 1);
        sum0 += __shfl_xor_sync(0xffffffffu, sum0, 2);
        sum8 += __shfl_xor_sync(0xffffffffu, sum8, 1);
        sum8 += __shfl_xor_sync(0xffffffffu, sum8, 2);
        lsum0 = lsum0 * al0 + sum0;
        lsum8 = lsum8 * al8 + sum8;
#pragma unroll
        for (int ni = 0; ni < 8; ++ni) {
            oacc[ni][0] *= al0; oacc[ni][1] *= al0;
            oacc[ni][2] *= al8; oacc[ni][3] *= al8;
        }

        // --- pack P ---
        uint32_t ph01[8], pl01[8], ph23[8], pl23[8];
#pragma unroll
        for (int ni = 0; ni < 8; ++ni) {
            const float h0 = bf16val(sv[ni][0]), h1 = bf16val(sv[ni][1]);
            ph01[ni] = pk2(h0, h1);
            pl01[ni] = pk2(sv[ni][0] - h0, sv[ni][1] - h1);
            const float h2 = bf16val(sv[ni][2]), h3 = bf16val(sv[ni][3]);
            ph23[ni] = pk2(h2, h3);
            pl23[ni] = pk2(sv[ni][2] - h2, sv[ni][3] - h3);
        }

        // --- O += P V (3x split) ---
#pragma unroll
        for (int j = 0; j < 4; ++j) {
            const int kb = j * 8;
            uint32_t ah[4]  = { ph01[2 * j], ph23[2 * j], ph01[2 * j + 1], ph23[2 * j + 1] };
            uint32_t alr[4] = { pl01[2 * j], pl23[2 * j], pl01[2 * j + 1], pl23[2 * j + 1] };
#pragma unroll
            for (int ni = 0; ni < 8; ++ni) {
                const int c0 = ni * 8 + g;
                const uint2 v0 = Vp[(kb + tg) * 68 + c0];
                const uint2 v1 = Vp[(kb + tg + 4) * 68 + c0];
                uint32_t bh[2] = { v0.x, v1.x };
                uint32_t bl[2] = { v0.y, v1.y };
                mma16816(oacc[ni], ah, bh);
                mma16816(oacc[ni], ah, bl);
                mma16816(oacc[ni], alr, bh);
            }
        }

        __syncthreads();   // stage (t&1) fully consumed before overwrite
        if (t + 2 < TTOT) AT_LOAD((t + 2) & 1, t + 2);
    }
#undef AT_LOAD

    // --- epilogue: normalize, stage per-warp [64 dk][17], coalesced store ---
    __syncthreads();
    const float inv0 = 1.f / lsum0, inv8 = 1.f / lsum8;
    float* os = (float*)smu2 + warp * (64 * 17);
#pragma unroll
    for (int ni = 0; ni < 8; ++ni) {
        const int dk0 = ni * 8 + tg * 2;
        os[(dk0 + 0) * 17 + g]     = oacc[ni][0] * inv0;
        os[(dk0 + 1) * 17 + g]     = oacc[ni][1] * inv0;
        os[(dk0 + 0) * 17 + 8 + g] = oacc[ni][2] * inv8;
        os[(dk0 + 1) * 17 + 8 + g] = oacc[ni][3] * inv8;
    }
    __syncwarp();
#pragma unroll
    for (int t = 0; t < 2; ++t) {
        const int dk = lane * 2 + t;
        float* dst = g_x + ((size_t)b * DD + (size_t)dk * HH + h) * NN + n0 + rb;
        const float* src = os + dk * 17;
#pragma unroll
        for (int q4 = 0; q4 < 4; ++q4)
            *(float4*)(dst + q4 * 4) =
                make_float4(src[q4 * 4], src[q4 * 4 + 1], src[q4 * 4 + 2], src[q4 * 4 + 3]);
    }
}

// ---------------------------------------------------------------------------
// Launch (order puts attention at launch #6 = ncu's -s 5 -c 1 capture)
// ---------------------------------------------------------------------------
extern "C" void kernel_launch(void* const* d_in, const int* in_sizes, int n_in,
                              void* d_out, int out_size)
{
    const float* init_query = (const float*)d_in[0];
    const float* key_t      = (const float*)d_in[1];
    const float* value      = (const float*)d_in[2];
    const int*   mask       = (const int*)  d_in[3];
    const float* Wq    = (const float*)d_in[4];
    const float* bq    = (const float*)d_in[5];
    const float* Wk    = (const float*)d_in[6];
    const float* bk    = (const float*)d_in[7];
    const float* Wv    = (const float*)d_in[8];
    const float* bv    = (const float*)d_in[9];
    const float* Wm    = (const float*)d_in[10];
    const float* bm    = (const float*)d_in[11];
    const float* W1    = (const float*)d_in[12];
    const float* b1    = (const float*)d_in[13];
    const float* gamma = (const float*)d_in[14];
    const float* beta  = (const float*)d_in[15];
    const float* rmean = (const float*)d_in[16];
    const float* rvar  = (const float*)d_in[17];
    const float* W2    = (const float*)d_in[18];
    const float* b2    = (const float*)d_in[19];
    float* out = (float*)d_out;

    float *p_x, *p_xm, *p_h;
    uint2 *p_qp, *p_kp, *p_vp;
    cudaGetSymbolAddress((void**)&p_x,  g_x);
    cudaGetSymbolAddress((void**)&p_xm, g_xm);
    cudaGetSymbolAddress((void**)&p_h,  g_h);
    cudaGetSymbolAddress((void**)&p_qp, g_qp);
    cudaGetSymbolAddress((void**)&p_kp, g_kp);
    cudaGetSymbolAddress((void**)&p_vp, g_vp);

    cudaFuncSetAttribute(attn_tc_kernel,
                         cudaFuncAttributeMaxDynamicSharedMemorySize, ATT_SMEM);
    cudaFuncSetAttribute(proj_kernel<2>,
                         cudaFuncAttributeMaxDynamicSharedMemorySize, GEMM_SMEM);
    cudaFuncSetAttribute(proj_kernel<3>,
                         cudaFuncAttributeMaxDynamicSharedMemorySize, GEMM_SMEM);
    cudaFuncSetAttribute(gemm_kernel<0>,
                         cudaFuncAttributeMaxDynamicSharedMemorySize, GEMM_SMEM);
    cudaFuncSetAttribute(gemm_kernel<1>,
                         cudaFuncAttributeMaxDynamicSharedMemorySize, GEMM_SMEM);

    // 1-3) projections -> packed split-bf16 Q/K/V
    proj_kernel<2><<<dim3(16, 4, BB), 256, GEMM_SMEM>>>(init_query, Wq, bq, p_qp);
    proj_kernel<2><<<dim3(16, 4, BB), 256, GEMM_SMEM>>>(key_t,      Wk, bk, p_kp);
    proj_kernel<3><<<dim3(16, 4, BB), 256, GEMM_SMEM>>>(value,      Wv, bv, p_vp);
    // 4-5) mask -> bitmask (two halves)
    maskbits_kernel<<<256, 256>>>(mask, 0);
    maskbits_kernel<<<256, 256>>>(mask, 65536);
    // 6) flash attention -> g_x  (this is the launch ncu captures)
    attn_tc_kernel<<<dim3(NN / 64, HH, BB), 128, ATT_SMEM>>>();
    // 7) merge conv
    gemm_kernel<0><<<dim3(16, 4, BB), 256, GEMM_SMEM>>>(Wm, p_x, nullptr, bm,
                                                        nullptr, nullptr, nullptr, nullptr,
                                                        p_xm, DD, DD);
    // 8) W1 @ [xm ; init_query] + BN + ReLU
    gemm_kernel<1><<<dim3(16, 8, BB), 256, GEMM_SMEM>>>(W1, p_xm, init_query, b1,
                                                        rmean, rvar, gamma, beta,
                                                        p_h, DD2, DD2);
    // 9) out = W2 @ h + b2
    gemm_kernel<0><<<dim3(16, 4, BB), 256, GEMM_SMEM>>>(W2, p_h, nullptr, b2,
                                                        nullptr, nullptr, nullptr, nullptr,
                                                        out, DD, DD2);
}

// round 16
// speedup vs baseline: 1.1124x; 1.1124x over previous
#include <cuda_runtime.h>
#include <cuda_bf16.h>
#include <math.h>
#include <float.h>
#include <stdint.h>

// Problem constants
#define BB   2
#define DD   512
#define NN   2048
#define HH   8
#define DD2  1024
#define EPSV 1e-5f
#define SCALE2 0.18033688011112042f   // 0.125 * log2(e)

// ---------------------------------------------------------------------------
// Scratch
// ---------------------------------------------------------------------------
__device__ uint2 g_qp[BB * HH * 32 * NN];    // attention Q [b,h][dkp][n]  (hi,lo) pairs along dk
__device__ uint2 g_kp[BB * HH * 32 * NN];    // attention K
__device__ uint2 g_vp[BB * HH * 1024 * 64];  // attention V [b,h][np][dk]  pairs along n
__device__ float g_x [BB * DD  * NN];
__device__ float g_xm[BB * DD  * NN];
__device__ float g_h [BB * DD2 * NN];
__device__ unsigned long long g_mbits[BB * NN * 32];  // 1 MB bitmask

// ---------------------------------------------------------------------------
// Helpers
// ---------------------------------------------------------------------------
__device__ __forceinline__ uint32_t pk2(float lo, float hi) {
    uint32_t r;
    asm("cvt.rn.bf16x2.f32 %0, %1, %2;" : "=r"(r) : "f"(hi), "f"(lo));
    return r;
}
__device__ __forceinline__ float bf16val(float x) {
    return __bfloat162float(__float2bfloat16_rn(x));
}
__device__ __forceinline__ void mma16816(float c[4], const uint32_t a[4], const uint32_t b[2]) {
    asm volatile(
        "mma.sync.aligned.m16n8k16.row.col.f32.bf16.bf16.f32 "
        "{%0,%1,%2,%3}, {%4,%5,%6,%7}, {%8,%9}, {%0,%1,%2,%3};"
        : "+f"(c[0]), "+f"(c[1]), "+f"(c[2]), "+f"(c[3])
        : "r"(a[0]), "r"(a[1]), "r"(a[2]), "r"(a[3]), "r"(b[0]), "r"(b[1]));
}

// ---------------------------------------------------------------------------
// Mask -> bitmask pre-kernel. word (b, r, w) covers key cols w*64..w*64+63.
// ---------------------------------------------------------------------------
__global__ void maskbits_kernel(const int* __restrict__ mask)
{
    const int idx = blockIdx.x * 256 + threadIdx.x;   // BB*NN*32 = 131072
    const int b = idx >> 16;
    const int r = (idx >> 5) & (NN - 1);
    const int w = idx & 31;
    const int4* mp = (const int4*)(mask + ((size_t)b * NN + r) * NN + w * 64);
    unsigned long long bits = 0ULL;
#pragma unroll
    for (int i = 0; i < 16; ++i) {
        const int4 m4 = mp[i];
        bits |= (unsigned long long)(m4.x != 0) << (4 * i + 0);
        bits |= (unsigned long long)(m4.y != 0) << (4 * i + 1);
        bits |= (unsigned long long)(m4.z != 0) << (4 * i + 2);
        bits |= (unsigned long long)(m4.w != 0) << (4 * i + 3);
    }
    g_mbits[idx] = bits;
}

// ---------------------------------------------------------------------------
// Tensor-core GEMM (R7/R11 config, measured best): CTA 128x128, k-step 32,
// 256 threads, 8 warps (2m x 4n), warp tile 64x32. 2-stage double buffer +
// reg prefetch. 3xBF16 split. MODE 0: fp32 + bias. MODE 1: concat + BN + ReLU.
// MODE 2: packed Q/K epilogue ([h][dkp][n] uint2). MODE 3: packed V epilogue.
// Stage (words): AH[0,2560) AL[2560,5120) BH[5120,7232) BL[7232,9344)
// ---------------------------------------------------------------------------
#define GW_STAGE 9344
#define GEMM_SMEM (2 * GW_STAGE * 4)

template <int MODE>
__device__ __forceinline__ void gemm_body_tc(
    const float* __restrict__ W, const float* __restrict__ X,
    const float* __restrict__ X2, const float* __restrict__ bias,
    const float* __restrict__ rmean, const float* __restrict__ rvar,
    const float* __restrict__ gam,   const float* __restrict__ bet,
    void* __restrict__ outv, int O, int I)
{
    extern __shared__ uint32_t gsm[];

    const int tid  = threadIdx.x;
    const int lane = tid & 31, warp = tid >> 5;
    const int g = lane >> 2, tg = lane & 3;
    const int n0 = blockIdx.x * 128, o0 = blockIdx.y * 128;
    const int wm = (warp >> 2) * 64;
    const int wn = (warp & 3) * 32;

    float acc[4][4][4];
#pragma unroll
    for (int mi = 0; mi < 4; ++mi)
#pragma unroll
        for (int ni = 0; ni < 4; ++ni)
#pragma unroll
            for (int t = 0; t < 4; ++t) acc[mi][ni][t] = 0.f;

    float4 pa[4], pbx0[2], pbx1[2];

#define G_LDG(K0) do {                                                         \
    _Pragma("unroll")                                                          \
    for (int s = 0; s < 4; ++s) {                                              \
        const int u = tid + s * 256;                                           \
        const int o = u >> 3;                                                  \
        const int kc = (u & 7) << 2;                                           \
        pa[s] = *(const float4*)(W + (size_t)(o0 + o) * I + (K0) + kc);        \
    }                                                                          \
    _Pragma("unroll")                                                          \
    for (int s = 0; s < 2; ++s) {                                              \
        const int u = tid + s * 256;                                           \
        const int kp = u >> 5;                                                 \
        const int nc = (u & 31) << 2;                                          \
        const int row0 = (K0) + kp * 2;                                        \
        const float *s0p, *s1p;                                                \
        if (MODE == 1) {                                                       \
            s0p = (row0 < DD) ? (X + (size_t)row0 * NN)                        \
                              : (X2 + (size_t)(row0 - DD) * NN);               \
            const int row1 = row0 + 1;                                         \
            s1p = (row1 < DD) ? (X + (size_t)row1 * NN)                        \
                              : (X2 + (size_t)(row1 - DD) * NN);               \
        } else {                                                               \
            s0p = X + (size_t)row0 * NN;                                       \
            s1p = s0p + NN;                                                    \
        }                                                                      \
        pbx0[s] = *(const float4*)(s0p + n0 + nc);                             \
        pbx1[s] = *(const float4*)(s1p + n0 + nc);                             \
    } } while (0)

#define G_STS(ST) do {                                                         \
    uint32_t* AHp = gsm + (ST) * GW_STAGE;                                     \
    uint32_t* ALp = AHp + 2560;                                                \
    uint32_t* BHp = AHp + 5120;                                                \
    uint32_t* BLp = AHp + 7232;                                                \
    _Pragma("unroll")                                                          \
    for (int s = 0; s < 4; ++s) {                                              \
        const int u = tid + s * 256;                                           \
        const int o = u >> 3;                                                  \
        const int kc = (u & 7) << 2;                                           \
        const float4 w4 = pa[s];                                               \
        const float hx = bf16val(w4.x), hy = bf16val(w4.y);                    \
        const float hz = bf16val(w4.z), hw = bf16val(w4.w);                    \
        *(uint2*)&AHp[o * 20 + (kc >> 1)] = make_uint2(pk2(hx, hy), pk2(hz, hw)); \
        *(uint2*)&ALp[o * 20 + (kc >> 1)] =                                    \
            make_uint2(pk2(w4.x - hx, w4.y - hy), pk2(w4.z - hz, w4.w - hw));  \
    }                                                                          \
    _Pragma("unroll")                                                          \
    for (int s = 0; s < 2; ++s) {                                              \
        const int u = tid + s * 256;                                           \
        const int kp = u >> 5;                                                 \
        const int nc = (u & 31) << 2;                                          \
        const float4 x0 = pbx0[s], x1 = pbx1[s];                               \
        const float h0x = bf16val(x0.x), h0y = bf16val(x0.y),                  \
                    h0z = bf16val(x0.z), h0w = bf16val(x0.w);                  \
        const float h1x = bf16val(x1.x), h1y = bf16val(x1.y),                  \
                    h1z = bf16val(x1.z), h1w = bf16val(x1.w);                  \
        uint4 hv, lv;                                                          \
        hv.x = pk2(h0x, h1x); hv.y = pk2(h0y, h1y);                            \
        hv.z = pk2(h0z, h1z); hv.w = pk2(h0w, h1w);                            \
        lv.x = pk2(x0.x - h0x, x1.x - h1x); lv.y = pk2(x0.y - h0y, x1.y - h1y);\
        lv.z = pk2(x0.z - h0z, x1.z - h1z); lv.w = pk2(x0.w - h0w, x1.w - h1w);\
        *(uint4*)&BHp[kp * 132 + nc] = hv;                                     \
        *(uint4*)&BLp[kp * 132 + nc] = lv;                                     \
    } } while (0)

    const int T = I / 32;
    G_LDG(0);
    G_STS(0);
    G_LDG(32);
    __syncthreads();

    for (int t = 0; t < T; ++t) {
        const uint32_t* AHp = gsm + (t & 1) * GW_STAGE;
        const uint32_t* ALp = AHp + 2560;
        const uint32_t* BHp = AHp + 5120;
        const uint32_t* BLp = AHp + 7232;
#pragma unroll
        for (int ks = 0; ks < 2; ++ks) {
            const int kb = ks * 8;
            uint32_t ah[4][4], al[4][4];
#pragma unroll
            for (int mi = 0; mi < 4; ++mi) {
                const int r0 = wm + mi * 16 + g;
                ah[mi][0] = AHp[r0 * 20 + kb + tg];
                ah[mi][1] = AHp[(r0 + 8) * 20 + kb + tg];
                ah[mi][2] = AHp[r0 * 20 + kb + tg + 4];
                ah[mi][3] = AHp[(r0 + 8) * 20 + kb + tg + 4];
                al[mi][0] = ALp[r0 * 20 + kb + tg];
                al[mi][1] = ALp[(r0 + 8) * 20 + kb + tg];
                al[mi][2] = ALp[r0 * 20 + kb + tg + 4];
                al[mi][3] = ALp[(r0 + 8) * 20 + kb + tg + 4];
            }
#pragma unroll
            for (int ni = 0; ni < 4; ++ni) {
                const int c0 = wn + ni * 8 + g;
                uint32_t bh[2] = { BHp[(kb + tg) * 132 + c0], BHp[(kb + tg + 4) * 132 + c0] };
                uint32_t bl[2] = { BLp[(kb + tg) * 132 + c0], BLp[(kb + tg + 4) * 132 + c0] };
#pragma unroll
                for (int mi = 0; mi < 4; ++mi) {
                    mma16816(acc[mi][ni], ah[mi], bh);
                    mma16816(acc[mi][ni], ah[mi], bl);
                    mma16816(acc[mi][ni], al[mi], bh);
                }
            }
        }
        if (t + 1 < T) {
            G_STS((t + 1) & 1);
            if (t + 2 < T) G_LDG((t + 2) * 32);
        }
        __syncthreads();
    }
#undef G_LDG
#undef G_STS

    // --- epilogues ---
    if (MODE <= 1) {
        float* out = (float*)outv;
#pragma unroll
        for (int mi = 0; mi < 4; ++mi) {
#pragma unroll
            for (int rr = 0; rr < 2; ++rr) {
                const int o = o0 + wm + mi * 16 + rr * 8 + g;
                const float bi = bias[o];
                float sc = 1.f, sh = bi;
                if (MODE == 1) {
                    const float s = gam[o] * rsqrtf(rvar[o] + EPSV);
                    sc = s;
                    sh = (bi - rmean[o]) * s + bet[o];
                }
#pragma unroll
                for (int ni = 0; ni < 4; ++ni) {
                    float v0 = acc[mi][ni][rr * 2 + 0] * sc + sh;
                    float v1 = acc[mi][ni][rr * 2 + 1] * sc + sh;
                    if (MODE == 1) { v0 = fmaxf(v0, 0.f); v1 = fmaxf(v1, 0.f); }
                    *(float2*)(out + (size_t)o * NN + n0 + wn + ni * 8 + tg * 2) =
                        make_float2(v0, v1);
                }
            }
        }
    } else if (MODE == 2) {
        // Q/K pack: pairs along dk (channels o_e and o_e+8 -> dk, dk+1, same h).
        uint2* outp = (uint2*)outv;
#pragma unroll
        for (int mi = 0; mi < 4; ++mi) {
            const int o_e = o0 + wm + mi * 16 + g;       // o_e & 8 == 0
            const float be = bias[o_e], bo = bias[o_e + 8];
            const int hh = o_e & 7, dkp = o_e >> 4;
            uint2* rowp = outp + ((size_t)hh * 32 + dkp) * NN;
#pragma unroll
            for (int ni = 0; ni < 4; ++ni) {
                const float v00 = acc[mi][ni][0] + be, v01 = acc[mi][ni][1] + be;
                const float v10 = acc[mi][ni][2] + bo, v11 = acc[mi][ni][3] + bo;
                const float h00 = bf16val(v00), h01 = bf16val(v01);
                const float h10 = bf16val(v10), h11 = bf16val(v11);
                uint4 pv;
                pv.x = pk2(h00, h10); pv.y = pk2(v00 - h00, v10 - h10);
                pv.z = pk2(h01, h11); pv.w = pk2(v01 - h01, v11 - h11);
                *(uint4*)(rowp + n0 + wn + ni * 8 + tg * 2) = pv;
            }
        }
    } else {
        // V pack: pairs along n. Layout [h][np][dk].
        uint2* outp = (uint2*)outv;
#pragma unroll
        for (int mi = 0; mi < 4; ++mi) {
#pragma unroll
            for (int rr = 0; rr < 2; ++rr) {
                const int o = o0 + wm + mi * 16 + rr * 8 + g;
                const float bo = bias[o];
                const int hh = o & 7, dk = o >> 3;
                uint2* colp = outp + (size_t)hh * 1024 * 64 + dk;
#pragma unroll
                for (int ni = 0; ni < 4; ++ni) {
                    const float va = acc[mi][ni][rr * 2 + 0] + bo;
                    const float vb = acc[mi][ni][rr * 2 + 1] + bo;
                    const float ha = bf16val(va), hb2 = bf16val(vb);
                    uint2 val;
                    val.x = pk2(ha, hb2);
                    val.y = pk2(va - ha, vb - hb2);
                    const int np = (n0 + wn + ni * 8 + tg * 2) >> 1;
                    colp[(size_t)np * 64] = val;
                }
            }
        }
    }
}

__global__ __launch_bounds__(256)
void qkv_kernel(const float* __restrict__ xq, const float* __restrict__ xk,
                const float* __restrict__ xv,
                const float* __restrict__ Wq, const float* __restrict__ bq,
                const float* __restrict__ Wk, const float* __restrict__ bk,
                const float* __restrict__ Wv, const float* __restrict__ bv)
{
    const int z = blockIdx.z, b = z & 1, sel = z >> 1;
    if (sel == 0) {
        gemm_body_tc<2>(Wq, xq + (size_t)b * DD * NN, nullptr, bq,
                        nullptr, nullptr, nullptr, nullptr,
                        (void*)(g_qp + (size_t)b * HH * 32 * NN), DD, DD);
    } else if (sel == 1) {
        gemm_body_tc<2>(Wk, xk + (size_t)b * DD * NN, nullptr, bk,
                        nullptr, nullptr, nullptr, nullptr,
                        (void*)(g_kp + (size_t)b * HH * 32 * NN), DD, DD);
    } else {
        gemm_body_tc<3>(Wv, xv + (size_t)b * DD * NN, nullptr, bv,
                        nullptr, nullptr, nullptr, nullptr,
                        (void*)(g_vp + (size_t)b * HH * 1024 * 64), DD, DD);
    }
}

template <int MODE>
__global__ __launch_bounds__(256)
void gemm_kernel(const float* __restrict__ W, const float* __restrict__ X,
                 const float* __restrict__ X2, const float* __restrict__ bias,
                 const float* __restrict__ rmean, const float* __restrict__ rvar,
                 const float* __restrict__ gam,   const float* __restrict__ bet,
                 float* __restrict__ out, int O, int I)
{
    const int b = blockIdx.z;
    const size_t xs = (MODE == 1) ? (size_t)DD * NN : (size_t)I * NN;
    gemm_body_tc<MODE>(W, X + (size_t)b * xs,
                       (MODE == 1) ? (X2 + (size_t)b * DD * NN) : nullptr,
                       bias, rmean, rvar, gam, bet,
                       (void*)(out + (size_t)b * O * NN), O, I);
}

// ---------------------------------------------------------------------------
// Flash attention on pre-packed Q/K/V (R11 structure, exp2-domain softmax).
// CTA: 64 q-rows x (b,h), 128 threads = 4 warps x 16 rows.
// Smem (uint2): Qp[32][76] = 2432 | stage s at 2432 + s*4864:
//   Kp[32][76] | Vp[32][76]  (fragment LDS.64 conflict-free at stride 76)
// ---------------------------------------------------------------------------
#define AS_STAGE 4864
#define ATT_SMEM ((2432 + 2 * AS_STAGE) * 8)   // 97280 B

__global__ __launch_bounds__(128)
void attn_tc_kernel()
{
    extern __shared__ uint2 smu2[];
    uint2* Qp = smu2;

    const int tid  = threadIdx.x;
    const int lane = tid & 31, warp = tid >> 5;
    const int g = lane >> 2, tg = lane & 3;
    const int b = blockIdx.z, h = blockIdx.y, n0 = blockIdx.x * 64;
    const int rb = warp * 16;
    const int lr8 = tid >> 3;          // 0..15 loader row base
    const int lc8 = (tid & 7) * 2;     // 0,2,..,14 loader col base (uint2)

    const uint2* qbase = g_qp + ((size_t)(b * HH + h) * 32) * NN;
    const uint2* kbase = g_kp + ((size_t)(b * HH + h) * 32) * NN;
    const uint2* vbase = g_vp + ((size_t)(b * HH + h) * 1024) * 64;

    // --- load Q tile [dkp][r]: full 32x64 copy ---
#pragma unroll
    for (int jr = 0; jr < 2; ++jr)
#pragma unroll
        for (int jc = 0; jc < 4; ++jc) {
            const int row = lr8 + 16 * jr;
            const int col = lc8 + 16 * jc;
            *(uint4*)&Qp[row * 76 + col] =
                *(const uint4*)(qbase + (size_t)row * NN + n0 + col);
        }

    float oacc[8][4];
#pragma unroll
    for (int ni = 0; ni < 8; ++ni)
#pragma unroll
        for (int t = 0; t < 4; ++t) oacc[ni][t] = 0.f;
    float mrow0 = -INFINITY, mrow8 = -INFINITY, lsum0 = 0.f, lsum8 = 0.f;

    const size_t mrowbase0 = ((size_t)b * NN + n0 + rb + g) * 32;
    const size_t mrowbase8 = mrowbase0 + 8 * 32;

    uint4 pk4[8], pv4[8];

#define AT_LDG(M0) do {                                                        \
    _Pragma("unroll")                                                          \
    for (int jr = 0; jr < 2; ++jr)                                             \
        _Pragma("unroll")                                                      \
        for (int jc = 0; jc < 4; ++jc) {                                       \
            const int row = lr8 + 16 * jr;                                     \
            const int col = lc8 + 16 * jc;                                     \
            pk4[jr * 4 + jc] = *(const uint4*)(kbase + (size_t)row * NN + (M0) + col); \
            pv4[jr * 4 + jc] = *(const uint4*)(vbase + (size_t)(((M0) >> 1) + row) * 64 + col); \
        } } while (0)

#define AT_STS(ST) do {                                                        \
    uint2* Kst = smu2 + 2432 + (ST) * AS_STAGE;                                \
    uint2* Vst = Kst + 2432;                                                   \
    _Pragma("unroll")                                                          \
    for (int jr = 0; jr < 2; ++jr)                                             \
        _Pragma("unroll")                                                      \
        for (int jc = 0; jc < 4; ++jc) {                                       \
            const int row = lr8 + 16 * jr;                                     \
            const int col = lc8 + 16 * jc;                                     \
            *(uint4*)&Kst[row * 76 + col] = pk4[jr * 4 + jc];                  \
            *(uint4*)&Vst[row * 76 + col] = pv4[jr * 4 + jc];                  \
        } } while (0)

    AT_LDG(0);
    AT_STS(0);
    AT_LDG(64);
    __syncthreads();

    for (int t = 0; t < NN / 64; ++t) {
        const int m0 = t * 64;
        const uint2* Kp = smu2 + 2432 + (t & 1) * AS_STAGE;
        const uint2* Vp = Kp + 2432;

        // --- S = Q K^T (3x split) ---
        float sv[8][4];
#pragma unroll
        for (int ni = 0; ni < 8; ++ni)
#pragma unroll
            for (int tt = 0; tt < 4; ++tt) sv[ni][tt] = 0.f;
#pragma unroll
        for (int ks = 0; ks < 4; ++ks) {
            const int kb = ks * 8;
            const int r0 = rb + g;
            const uint2 q0 = Qp[(kb + tg) * 76 + r0];
            const uint2 q1 = Qp[(kb + tg) * 76 + r0 + 8];
            const uint2 q2 = Qp[(kb + tg + 4) * 76 + r0];
            const uint2 q3 = Qp[(kb + tg + 4) * 76 + r0 + 8];
            uint32_t qh[4] = { q0.x, q1.x, q2.x, q3.x };
            uint32_t ql[4] = { q0.y, q1.y, q2.y, q3.y };
#pragma unroll
            for (int ni = 0; ni < 8; ++ni) {
                const int c0 = ni * 8 + g;
                const uint2 k0 = Kp[(kb + tg) * 76 + c0];
                const uint2 k1 = Kp[(kb + tg + 4) * 76 + c0];
                uint32_t bh[2] = { k0.x, k1.x };
                uint32_t bl[2] = { k0.y, k1.y };
                mma16816(sv[ni], qh, bh);
                mma16816(sv[ni], qh, bl);
                mma16816(sv[ni], ql, bh);
            }
        }

        // --- mask + scale into exp2 domain ---
        const unsigned long long w0 = g_mbits[mrowbase0 + (m0 >> 6)];
        const unsigned long long w8 = g_mbits[mrowbase8 + (m0 >> 6)];
#pragma unroll
        for (int ni = 0; ni < 8; ++ni) {
            const int cb = ni * 8 + tg * 2;
            sv[ni][0] = ((w0 >> cb) & 1ULL)       ? sv[ni][0] * SCALE2 : -1e9f;
            sv[ni][1] = ((w0 >> (cb + 1)) & 1ULL) ? sv[ni][1] * SCALE2 : -1e9f;
            sv[ni][2] = ((w8 >> cb) & 1ULL)       ? sv[ni][2] * SCALE2 : -1e9f;
            sv[ni][3] = ((w8 >> (cb + 1)) & 1ULL) ? sv[ni][3] * SCALE2 : -1e9f;
        }

        // --- online softmax (exp2 domain) ---
        float mx0 = -INFINITY, mx8 = -INFINITY;
#pragma unroll
        for (int ni = 0; ni < 8; ++ni) {
            mx0 = fmaxf(mx0, fmaxf(sv[ni][0], sv[ni][1]));
            mx8 = fmaxf(mx8, fmaxf(sv[ni][2], sv[ni][3]));
        }
        mx0 = fmaxf(mx0, __shfl_xor_sync(0xffffffffu, mx0, 1));
        mx0 = fmaxf(mx0, __shfl_xor_sync(0xffffffffu, mx0, 2));
        mx8 = fmaxf(mx8, __shfl_xor_sync(0xffffffffu, mx8, 1));
        mx8 = fmaxf(mx8, __shfl_xor_sync(0xffffffffu, mx8, 2));
        const float mn0 = fmaxf(mrow0, mx0), mn8 = fmaxf(mrow8, mx8);
        const float al0 = exp2f(mrow0 - mn0), al8 = exp2f(mrow8 - mn8);
        mrow0 = mn0; mrow8 = mn8;
        float sum0 = 0.f, sum8 = 0.f;
#pragma unroll
        for (int ni = 0; ni < 8; ++ni) {
            sv[ni][0] = exp2f(sv[ni][0] - mn0); sum0 += sv[ni][0];
            sv[ni][1] = exp2f(sv[ni][1] - mn0); sum0 += sv[ni][1];
            sv[ni][2] = exp2f(sv[ni][2] - mn8); sum8 += sv[ni][2];
            sv[ni][3] = exp2f(sv[ni][3] - mn8); sum8 += sv[ni][3];
        }
        sum0 += __shfl_xor_sync(0xffffffffu, sum0, 1);
        sum0 += __shfl_xor_sync(0xffffffffu, sum0, 2);
        sum8 += __shfl_xor_sync(0xffffffffu, sum8, 1);
        sum8 += __shfl_xor_sync(0xffffffffu, sum8, 2);
        lsum0 = lsum0 * al0 + sum0;
        lsum8 = lsum8 * al8 + sum8;
#pragma unroll
        for (int ni = 0; ni < 8; ++ni) {
            oacc[ni][0] *= al0; oacc[ni][1] *= al0;
            oacc[ni][2] *= al8; oacc[ni][3] *= al8;
        }

        // --- pack P ---
        uint32_t ph01[8], pl01[8], ph23[8], pl23[8];
#pragma unroll
        for (int ni = 0; ni < 8; ++ni) {
            const float h0 = bf16val(sv[ni][0]), h1 = bf16val(sv[ni][1]);
            ph01[ni] = pk2(h0, h1);
            pl01[ni] = pk2(sv[ni][0] - h0, sv[ni][1] - h1);
            const float h2 = bf16val(sv[ni][2]), h3 = bf16val(sv[ni][3]);
            ph23[ni] = pk2(h2, h3);
            pl23[ni] = pk2(sv[ni][2] - h2, sv[ni][3] - h3);
        }

        // --- O += P V (3x split) ---
#pragma unroll
        for (int j = 0; j < 4; ++j) {
            const int kb = j * 8;
            uint32_t ah[4]  = { ph01[2 * j], ph23[2 * j], ph01[2 * j + 1], ph23[2 * j + 1] };
            uint32_t alr[4] = { pl01[2 * j], pl23[2 * j], pl01[2 * j + 1], pl23[2 * j + 1] };
#pragma unroll
            for (int ni = 0; ni < 8; ++ni) {
                const int c0 = ni * 8 + g;
                const uint2 v0 = Vp[(kb + tg) * 76 + c0];
                const uint2 v1 = Vp[(kb + tg + 4) * 76 + c0];
                uint32_t bh[2] = { v0.x, v1.x };
                uint32_t bl[2] = { v0.y, v1.y };
                mma16816(oacc[ni], ah, bh);
                mma16816(oacc[ni], ah, bl);
                mma16816(oacc[ni], alr, bh);
            }
        }

        if (t + 1 < NN / 64) {
            AT_STS((t + 1) & 1);
            if (t + 2 < NN / 64) AT_LDG((t + 2) * 64);
        }
        __syncthreads();
    }
#undef AT_LDG
#undef AT_STS

    // --- epilogue: normalize, stage per-warp [64 dk][17], coalesced store ---
    const float inv0 = 1.f / lsum0, inv8 = 1.f / lsum8;
    float* os = (float*)smu2 + warp * (64 * 17);
#pragma unroll
    for (int ni = 0; ni < 8; ++ni) {
        const int dk0 = ni * 8 + tg * 2;
        os[(dk0 + 0) * 17 + g]     = oacc[ni][0] * inv0;
        os[(dk0 + 1) * 17 + g]     = oacc[ni][1] * inv0;
        os[(dk0 + 0) * 17 + 8 + g] = oacc[ni][2] * inv8;
        os[(dk0 + 1) * 17 + 8 + g] = oacc[ni][3] * inv8;
    }
    __syncwarp();
#pragma unroll
    for (int t = 0; t < 2; ++t) {
        const int dk = lane * 2 + t;
        float* dst = g_x + ((size_t)b * DD + (size_t)dk * HH + h) * NN + n0 + rb;
        const float* src = os + dk * 17;
#pragma unroll
        for (int q4 = 0; q4 < 4; ++q4)
            *(float4*)(dst + q4 * 4) =
                make_float4(src[q4 * 4], src[q4 * 4 + 1], src[q4 * 4 + 2], src[q4 * 4 + 3]);
    }
}

// ---------------------------------------------------------------------------
// Launch (R11 order restored)
// ---------------------------------------------------------------------------
extern "C" void kernel_launch(void* const* d_in, const int* in_sizes, int n_in,
                              void* d_out, int out_size)
{
    const float* init_query = (const float*)d_in[0];
    const float* key_t      = (const float*)d_in[1];
    const float* value      = (const float*)d_in[2];
    const int*   mask       = (const int*)  d_in[3];
    const float* Wq    = (const float*)d_in[4];
    const float* bq    = (const float*)d_in[5];
    const float* Wk    = (const float*)d_in[6];
    const float* bk    = (const float*)d_in[7];
    const float* Wv    = (const float*)d_in[8];
    const float* bv    = (const float*)d_in[9];
    const float* Wm    = (const float*)d_in[10];
    const float* bm    = (const float*)d_in[11];
    const float* W1    = (const float*)d_in[12];
    const float* b1    = (const float*)d_in[13];
    const float* gamma = (const float*)d_in[14];
    const float* beta  = (const float*)d_in[15];
    const float* rmean = (const float*)d_in[16];
    const float* rvar  = (const float*)d_in[17];
    const float* W2    = (const float*)d_in[18];
    const float* b2    = (const float*)d_in[19];
    float* out = (float*)d_out;

    float *p_x, *p_xm, *p_h;
    cudaGetSymbolAddress((void**)&p_x,  g_x);
    cudaGetSymbolAddress((void**)&p_xm, g_xm);
    cudaGetSymbolAddress((void**)&p_h,  g_h);

    cudaFuncSetAttribute(attn_tc_kernel,
                         cudaFuncAttributeMaxDynamicSharedMemorySize, ATT_SMEM);
    cudaFuncSetAttribute(qkv_kernel,
                         cudaFuncAttributeMaxDynamicSharedMemorySize, GEMM_SMEM);
    cudaFuncSetAttribute(gemm_kernel<0>,
                         cudaFuncAttributeMaxDynamicSharedMemorySize, GEMM_SMEM);
    cudaFuncSetAttribute(gemm_kernel<1>,
                         cudaFuncAttributeMaxDynamicSharedMemorySize, GEMM_SMEM);

    // 0) mask -> bitmask
    maskbits_kernel<<<512, 256>>>(mask);
    // 1) q/k/v projections -> packed split-bf16 Q/K/V
    qkv_kernel<<<dim3(16, 4, 6), 256, GEMM_SMEM>>>(init_query, key_t, value,
                                                   Wq, bq, Wk, bk, Wv, bv);
    // 2) flash attention -> g_x (fp32)
    attn_tc_kernel<<<dim3(NN / 64, HH, BB), 128, ATT_SMEM>>>();
    // 3) merge conv
    gemm_kernel<0><<<dim3(16, 4, BB), 256, GEMM_SMEM>>>(Wm, p_x, nullptr, bm,
                                                        nullptr, nullptr, nullptr, nullptr,
                                                        p_xm, DD, DD);
    // 4) W1 @ [xm ; init_query] + BN + ReLU
    gemm_kernel<1><<<dim3(16, 8, BB), 256, GEMM_SMEM>>>(W1, p_xm, init_query, b1,
                                                        rmean, rvar, gamma, beta,
                                                        p_h, DD2, DD2);
    // 5) out = W2 @ h + b2
    gemm_kernel<0><<<dim3(16, 4, BB), 256, GEMM_SMEM>>>(W2, p_h, nullptr, b2,
                                                        nullptr, nullptr, nullptr, nullptr,
                                                        out, DD, DD2);
}

// round 17
// speedup vs baseline: 1.2859x; 1.1560x over previous
#include <cuda_runtime.h>
#include <cuda_bf16.h>
#include <math.h>
#include <float.h>
#include <stdint.h>

// Problem constants
#define BB   2
#define DD   512
#define NN   2048
#define HH   8
#define DD2  1024
#define EPSV 1e-5f
#define SCALE2 0.18033688011112042f   // 0.125 * log2(e)

// ---------------------------------------------------------------------------
// Scratch
// ---------------------------------------------------------------------------
__device__ uint2 g_qp[BB * HH * 32 * NN];    // attention Q [b,h][dkp][n]  (hi,lo) pairs along dk
__device__ uint2 g_kp[BB * HH * 32 * NN];    // attention K
__device__ uint2 g_vp[BB * HH * 1024 * 64];  // attention V [b,h][np][dk]  pairs along n
__device__ float g_x [BB * DD  * NN];
__device__ float g_xm[BB * DD  * NN];
__device__ float g_h [BB * DD2 * NN];
__device__ unsigned long long g_mbits[BB * NN * 32];  // 1 MB bitmask

// ---------------------------------------------------------------------------
// Helpers
// ---------------------------------------------------------------------------
__device__ __forceinline__ uint32_t pk2(float lo, float hi) {
    uint32_t r;
    asm("cvt.rn.bf16x2.f32 %0, %1, %2;" : "=r"(r) : "f"(hi), "f"(lo));
    return r;
}
__device__ __forceinline__ float bf16val(float x) {
    return __bfloat162float(__float2bfloat16_rn(x));
}
__device__ __forceinline__ void mma16816(float c[4], const uint32_t a[4], const uint32_t b[2]) {
    asm volatile(
        "mma.sync.aligned.m16n8k16.row.col.f32.bf16.bf16.f32 "
        "{%0,%1,%2,%3}, {%4,%5,%6,%7}, {%8,%9}, {%0,%1,%2,%3};"
        : "+f"(c[0]), "+f"(c[1]), "+f"(c[2]), "+f"(c[3])
        : "r"(a[0]), "r"(a[1]), "r"(a[2]), "r"(a[3]), "r"(b[0]), "r"(b[1]));
}

// ---------------------------------------------------------------------------
// Mask -> bitmask pre-kernel. word (b, r, w) covers key cols w*64..w*64+63.
// ---------------------------------------------------------------------------
__global__ void maskbits_kernel(const int* __restrict__ mask)
{
    const int idx = blockIdx.x * 256 + threadIdx.x;   // BB*NN*32 = 131072
    const int b = idx >> 16;
    const int r = (idx >> 5) & (NN - 1);
    const int w = idx & 31;
    const int4* mp = (const int4*)(mask + ((size_t)b * NN + r) * NN + w * 64);
    unsigned long long bits = 0ULL;
#pragma unroll
    for (int i = 0; i < 16; ++i) {
        const int4 m4 = mp[i];
        bits |= (unsigned long long)(m4.x != 0) << (4 * i + 0);
        bits |= (unsigned long long)(m4.y != 0) << (4 * i + 1);
        bits |= (unsigned long long)(m4.z != 0) << (4 * i + 2);
        bits |= (unsigned long long)(m4.w != 0) << (4 * i + 3);
    }
    g_mbits[idx] = bits;
}

// ---------------------------------------------------------------------------
// Tensor-core GEMM (R7/R11 config, measured best): CTA 128x128, k-step 32,
// 256 threads, 8 warps (2m x 4n), warp tile 64x32. 2-stage double buffer +
// reg prefetch. 3xBF16 split. MODE 0: fp32 + bias. MODE 1: concat + BN + ReLU.
// MODE 2: packed Q/K epilogue ([h][dkp][n] uint2). MODE 3: packed V epilogue.
// Stage (words): AH[0,2560) AL[2560,5120) BH[5120,7232) BL[7232,9344)
// ---------------------------------------------------------------------------
#define GW_STAGE 9344
#define GEMM_SMEM (2 * GW_STAGE * 4)

template <int MODE>
__device__ __forceinline__ void gemm_body_tc(
    const float* __restrict__ W, const float* __restrict__ X,
    const float* __restrict__ X2, const float* __restrict__ bias,
    const float* __restrict__ rmean, const float* __restrict__ rvar,
    const float* __restrict__ gam,   const float* __restrict__ bet,
    void* __restrict__ outv, int O, int I)
{
    extern __shared__ uint32_t gsm[];

    const int tid  = threadIdx.x;
    const int lane = tid & 31, warp = tid >> 5;
    const int g = lane >> 2, tg = lane & 3;
    const int n0 = blockIdx.x * 128, o0 = blockIdx.y * 128;
    const int wm = (warp >> 2) * 64;
    const int wn = (warp & 3) * 32;

    float acc[4][4][4];
#pragma unroll
    for (int mi = 0; mi < 4; ++mi)
#pragma unroll
        for (int ni = 0; ni < 4; ++ni)
#pragma unroll
            for (int t = 0; t < 4; ++t) acc[mi][ni][t] = 0.f;

    float4 pa[4], pbx0[2], pbx1[2];

#define G_LDG(K0) do {                                                         \
    _Pragma("unroll")                                                          \
    for (int s = 0; s < 4; ++s) {                                              \
        const int u = tid + s * 256;                                           \
        const int o = u >> 3;                                                  \
        const int kc = (u & 7) << 2;                                           \
        pa[s] = *(const float4*)(W + (size_t)(o0 + o) * I + (K0) + kc);        \
    }                                                                          \
    _Pragma("unroll")                                                          \
    for (int s = 0; s < 2; ++s) {                                              \
        const int u = tid + s * 256;                                           \
        const int kp = u >> 5;                                                 \
        const int nc = (u & 31) << 2;                                          \
        const int row0 = (K0) + kp * 2;                                        \
        const float *s0p, *s1p;                                                \
        if (MODE == 1) {                                                       \
            s0p = (row0 < DD) ? (X + (size_t)row0 * NN)                        \
                              : (X2 + (size_t)(row0 - DD) * NN);               \
            const int row1 = row0 + 1;                                         \
            s1p = (row1 < DD) ? (X + (size_t)row1 * NN)                        \
                              : (X2 + (size_t)(row1 - DD) * NN);               \
        } else {                                                               \
            s0p = X + (size_t)row0 * NN;                                       \
            s1p = s0p + NN;                                                    \
        }                                                                      \
        pbx0[s] = *(const float4*)(s0p + n0 + nc);                             \
        pbx1[s] = *(const float4*)(s1p + n0 + nc);                             \
    } } while (0)

#define G_STS(ST) do {                                                         \
    uint32_t* AHp = gsm + (ST) * GW_STAGE;                                     \
    uint32_t* ALp = AHp + 2560;                                                \
    uint32_t* BHp = AHp + 5120;                                                \
    uint32_t* BLp = AHp + 7232;                                                \
    _Pragma("unroll")                                                          \
    for (int s = 0; s < 4; ++s) {                                              \
        const int u = tid + s * 256;                                           \
        const int o = u >> 3;                                                  \
        const int kc = (u & 7) << 2;                                           \
        const float4 w4 = pa[s];                                               \
        const float hx = bf16val(w4.x), hy = bf16val(w4.y);                    \
        const float hz = bf16val(w4.z), hw = bf16val(w4.w);                    \
        *(uint2*)&AHp[o * 20 + (kc >> 1)] = make_uint2(pk2(hx, hy), pk2(hz, hw)); \
        *(uint2*)&ALp[o * 20 + (kc >> 1)] =                                    \
            make_uint2(pk2(w4.x - hx, w4.y - hy), pk2(w4.z - hz, w4.w - hw));  \
    }                                                                          \
    _Pragma("unroll")                                                          \
    for (int s = 0; s < 2; ++s) {                                              \
        const int u = tid + s * 256;                                           \
        const int kp = u >> 5;                                                 \
        const int nc = (u & 31) << 2;                                          \
        const float4 x0 = pbx0[s], x1 = pbx1[s];                               \
        const float h0x = bf16val(x0.x), h0y = bf16val(x0.y),                  \
                    h0z = bf16val(x0.z), h0w = bf16val(x0.w);                  \
        const float h1x = bf16val(x1.x), h1y = bf16val(x1.y),                  \
                    h1z = bf16val(x1.z), h1w = bf16val(x1.w);                  \
        uint4 hv, lv;                                                          \
        hv.x = pk2(h0x, h1x); hv.y = pk2(h0y, h1y);                            \
        hv.z = pk2(h0z, h1z); hv.w = pk2(h0w, h1w);                            \
        lv.x = pk2(x0.x - h0x, x1.x - h1x); lv.y = pk2(x0.y - h0y, x1.y - h1y);\
        lv.z = pk2(x0.z - h0z, x1.z - h1z); lv.w = pk2(x0.w - h0w, x1.w - h1w);\
        *(uint4*)&BHp[kp * 132 + nc] = hv;                                     \
        *(uint4*)&BLp[kp * 132 + nc] = lv;                                     \
    } } while (0)

    const int T = I / 32;
    G_LDG(0);
    G_STS(0);
    G_LDG(32);
    __syncthreads();

    for (int t = 0; t < T; ++t) {
        const uint32_t* AHp = gsm + (t & 1) * GW_STAGE;
        const uint32_t* ALp = AHp + 2560;
        const uint32_t* BHp = AHp + 5120;
        const uint32_t* BLp = AHp + 7232;
#pragma unroll
        for (int ks = 0; ks < 2; ++ks) {
            const int kb = ks * 8;
            uint32_t ah[4][4], al[4][4];
#pragma unroll
            for (int mi = 0; mi < 4; ++mi) {
                const int r0 = wm + mi * 16 + g;
                ah[mi][0] = AHp[r0 * 20 + kb + tg];
                ah[mi][1] = AHp[(r0 + 8) * 20 + kb + tg];
                ah[mi][2] = AHp[r0 * 20 + kb + tg + 4];
                ah[mi][3] = AHp[(r0 + 8) * 20 + kb + tg + 4];
                al[mi][0] = ALp[r0 * 20 + kb + tg];
                al[mi][1] = ALp[(r0 + 8) * 20 + kb + tg];
                al[mi][2] = ALp[r0 * 20 + kb + tg + 4];
                al[mi][3] = ALp[(r0 + 8) * 20 + kb + tg + 4];
            }
#pragma unroll
            for (int ni = 0; ni < 4; ++ni) {
                const int c0 = wn + ni * 8 + g;
                uint32_t bh[2] = { BHp[(kb + tg) * 132 + c0], BHp[(kb + tg + 4) * 132 + c0] };
                uint32_t bl[2] = { BLp[(kb + tg) * 132 + c0], BLp[(kb + tg + 4) * 132 + c0] };
#pragma unroll
                for (int mi = 0; mi < 4; ++mi) {
                    mma16816(acc[mi][ni], ah[mi], bh);
                    mma16816(acc[mi][ni], ah[mi], bl);
                    mma16816(acc[mi][ni], al[mi], bh);
                }
            }
        }
        if (t + 1 < T) {
            G_STS((t + 1) & 1);
            if (t + 2 < T) G_LDG((t + 2) * 32);
        }
        __syncthreads();
    }
#undef G_LDG
#undef G_STS

    // --- epilogues ---
    if (MODE <= 1) {
        float* out = (float*)outv;
#pragma unroll
        for (int mi = 0; mi < 4; ++mi) {
#pragma unroll
            for (int rr = 0; rr < 2; ++rr) {
                const int o = o0 + wm + mi * 16 + rr * 8 + g;
                const float bi = bias[o];
                float sc = 1.f, sh = bi;
                if (MODE == 1) {
                    const float s = gam[o] * rsqrtf(rvar[o] + EPSV);
                    sc = s;
                    sh = (bi - rmean[o]) * s + bet[o];
                }
#pragma unroll
                for (int ni = 0; ni < 4; ++ni) {
                    float v0 = acc[mi][ni][rr * 2 + 0] * sc + sh;
                    float v1 = acc[mi][ni][rr * 2 + 1] * sc + sh;
                    if (MODE == 1) { v0 = fmaxf(v0, 0.f); v1 = fmaxf(v1, 0.f); }
                    *(float2*)(out + (size_t)o * NN + n0 + wn + ni * 8 + tg * 2) =
                        make_float2(v0, v1);
                }
            }
        }
    } else if (MODE == 2) {
        // Q/K pack: pairs along dk (channels o_e and o_e+8 -> dk, dk+1, same h).
        uint2* outp = (uint2*)outv;
#pragma unroll
        for (int mi = 0; mi < 4; ++mi) {
            const int o_e = o0 + wm + mi * 16 + g;       // o_e & 8 == 0
            const float be = bias[o_e], bo = bias[o_e + 8];
            const int hh = o_e & 7, dkp = o_e >> 4;
            uint2* rowp = outp + ((size_t)hh * 32 + dkp) * NN;
#pragma unroll
            for (int ni = 0; ni < 4; ++ni) {
                const float v00 = acc[mi][ni][0] + be, v01 = acc[mi][ni][1] + be;
                const float v10 = acc[mi][ni][2] + bo, v11 = acc[mi][ni][3] + bo;
                const float h00 = bf16val(v00), h01 = bf16val(v01);
                const float h10 = bf16val(v10), h11 = bf16val(v11);
                uint4 pv;
                pv.x = pk2(h00, h10); pv.y = pk2(v00 - h00, v10 - h10);
                pv.z = pk2(h01, h11); pv.w = pk2(v01 - h01, v11 - h11);
                *(uint4*)(rowp + n0 + wn + ni * 8 + tg * 2) = pv;
            }
        }
    } else {
        // V pack: pairs along n. Layout [h][np][dk].
        uint2* outp = (uint2*)outv;
#pragma unroll
        for (int mi = 0; mi < 4; ++mi) {
#pragma unroll
            for (int rr = 0; rr < 2; ++rr) {
                const int o = o0 + wm + mi * 16 + rr * 8 + g;
                const float bo = bias[o];
                const int hh = o & 7, dk = o >> 3;
                uint2* colp = outp + (size_t)hh * 1024 * 64 + dk;
#pragma unroll
                for (int ni = 0; ni < 4; ++ni) {
                    const float va = acc[mi][ni][rr * 2 + 0] + bo;
                    const float vb = acc[mi][ni][rr * 2 + 1] + bo;
                    const float ha = bf16val(va), hb2 = bf16val(vb);
                    uint2 val;
                    val.x = pk2(ha, hb2);
                    val.y = pk2(va - ha, vb - hb2);
                    const int np = (n0 + wn + ni * 8 + tg * 2) >> 1;
                    colp[(size_t)np * 64] = val;
                }
            }
        }
    }
}

__global__ __launch_bounds__(256)
void qkv_kernel(const float* __restrict__ xq, const float* __restrict__ xk,
                const float* __restrict__ xv,
                const float* __restrict__ Wq, const float* __restrict__ bq,
                const float* __restrict__ Wk, const float* __restrict__ bk,
                const float* __restrict__ Wv, const float* __restrict__ bv)
{
    const int z = blockIdx.z, b = z & 1, sel = z >> 1;
    if (sel == 0) {
        gemm_body_tc<2>(Wq, xq + (size_t)b * DD * NN, nullptr, bq,
                        nullptr, nullptr, nullptr, nullptr,
                        (void*)(g_qp + (size_t)b * HH * 32 * NN), DD, DD);
    } else if (sel == 1) {
        gemm_body_tc<2>(Wk, xk + (size_t)b * DD * NN, nullptr, bk,
                        nullptr, nullptr, nullptr, nullptr,
                        (void*)(g_kp + (size_t)b * HH * 32 * NN), DD, DD);
    } else {
        gemm_body_tc<3>(Wv, xv + (size_t)b * DD * NN, nullptr, bv,
                        nullptr, nullptr, nullptr, nullptr,
                        (void*)(g_vp + (size_t)b * HH * 1024 * 64), DD, DD);
    }
}

template <int MODE>
__global__ __launch_bounds__(256)
void gemm_kernel(const float* __restrict__ W, const float* __restrict__ X,
                 const float* __restrict__ X2, const float* __restrict__ bias,
                 const float* __restrict__ rmean, const float* __restrict__ rvar,
                 const float* __restrict__ gam,   const float* __restrict__ bet,
                 float* __restrict__ out, int O, int I)
{
    const int b = blockIdx.z;
    const size_t xs = (MODE == 1) ? (size_t)DD * NN : (size_t)I * NN;
    gemm_body_tc<MODE>(W, X + (size_t)b * xs,
                       (MODE == 1) ? (X2 + (size_t)b * DD * NN) : nullptr,
                       bias, rmean, rvar, gam, bet,
                       (void*)(out + (size_t)b * O * NN), O, I);
}

// ---------------------------------------------------------------------------
// Flash attention: Q-hi fragments in registers (lo(Q)*hi(K) term dropped in S;
// PV keeps full 3-term split). exp2-domain softmax. CTA: 64 q-rows x (b,h),
// 128 threads = 4 warps x 16 rows. Smem (uint2): stage s at s*4864:
//   Kp[32][76] | Vp[32][76]. Q staged through stage 0 before mainloop.
// ---------------------------------------------------------------------------
#define AS_STAGE 4864
#define ATT_SMEM (2 * AS_STAGE * 8)   // 77824 B

__global__ __launch_bounds__(128)
void attn_tc_kernel()
{
    extern __shared__ uint2 smu2[];

    const int tid  = threadIdx.x;
    const int lane = tid & 31, warp = tid >> 5;
    const int g = lane >> 2, tg = lane & 3;
    const int b = blockIdx.z, h = blockIdx.y, n0 = blockIdx.x * 64;
    const int rb = warp * 16;
    const int lr8 = tid >> 3;          // 0..15 loader row base
    const int lc8 = (tid & 7) * 2;     // 0,2,..,14 loader col base (uint2)

    const uint2* qbase = g_qp + ((size_t)(b * HH + h) * 32) * NN;
    const uint2* kbase = g_kp + ((size_t)(b * HH + h) * 32) * NN;
    const uint2* vbase = g_vp + ((size_t)(b * HH + h) * 1024) * 64;

    uint4 pk4[8], pv4[8];

#define AT_LDG(M0) do {                                                        \
    _Pragma("unroll")                                                          \
    for (int jr = 0; jr < 2; ++jr)                                             \
        _Pragma("unroll")                                                      \
        for (int jc = 0; jc < 4; ++jc) {                                       \
            const int row = lr8 + 16 * jr;                                     \
            const int col = lc8 + 16 * jc;                                     \
            pk4[jr * 4 + jc] = *(const uint4*)(kbase + (size_t)row * NN + (M0) + col); \
            pv4[jr * 4 + jc] = *(const uint4*)(vbase + (size_t)(((M0) >> 1) + row) * 64 + col); \
        } } while (0)

#define AT_STS(ST) do {                                                        \
    uint2* Kst = smu2 + (ST) * AS_STAGE;                                       \
    uint2* Vst = Kst + 2432;                                                   \
    _Pragma("unroll")                                                          \
    for (int jr = 0; jr < 2; ++jr)                                             \
        _Pragma("unroll")                                                      \
        for (int jc = 0; jc < 4; ++jc) {                                       \
            const int row = lr8 + 16 * jr;                                     \
            const int col = lc8 + 16 * jc;                                     \
            *(uint4*)&Kst[row * 76 + col] = pk4[jr * 4 + jc];                  \
            *(uint4*)&Vst[row * 76 + col] = pv4[jr * 4 + jc];                  \
        } } while (0)

    // Issue first K/V tile loads, then stage Q through stage-0 smem while
    // they are in flight; hoist Q-hi fragments to registers.
    AT_LDG(0);
    {
        uint2* Qs = smu2;
#pragma unroll
        for (int jr = 0; jr < 2; ++jr)
#pragma unroll
            for (int jc = 0; jc < 4; ++jc) {
                const int row = lr8 + 16 * jr;
                const int col = lc8 + 16 * jc;
                *(uint4*)&Qs[row * 76 + col] =
                    *(const uint4*)(qbase + (size_t)row * NN + n0 + col);
            }
    }
    __syncthreads();
    uint32_t qh[4][4];
    {
        const uint2* Qs = smu2;
        const int r0 = rb + g;
#pragma unroll
        for (int ks = 0; ks < 4; ++ks) {
            const int kb = ks * 8;
            qh[ks][0] = ((const uint32_t*)&Qs[(kb + tg) * 76 + r0])[0];
            qh[ks][1] = ((const uint32_t*)&Qs[(kb + tg) * 76 + r0 + 8])[0];
            qh[ks][2] = ((const uint32_t*)&Qs[(kb + tg + 4) * 76 + r0])[0];
            qh[ks][3] = ((const uint32_t*)&Qs[(kb + tg + 4) * 76 + r0 + 8])[0];
        }
    }
    __syncthreads();
    AT_STS(0);
    AT_LDG(64);

    float oacc[8][4];
#pragma unroll
    for (int ni = 0; ni < 8; ++ni)
#pragma unroll
        for (int t = 0; t < 4; ++t) oacc[ni][t] = 0.f;
    float mrow0 = -INFINITY, mrow8 = -INFINITY, lsum0 = 0.f, lsum8 = 0.f;

    const size_t mrowbase0 = ((size_t)b * NN + n0 + rb + g) * 32;
    const size_t mrowbase8 = mrowbase0 + 8 * 32;

    __syncthreads();

    for (int t = 0; t < NN / 64; ++t) {
        const int m0 = t * 64;
        const uint2* Kp = smu2 + (t & 1) * AS_STAGE;
        const uint2* Vp = Kp + 2432;

        // --- S = Q K^T (2-term split: hiQ*hiK + hiQ*loK) ---
        float sv[8][4];
#pragma unroll
        for (int ni = 0; ni < 8; ++ni)
#pragma unroll
            for (int tt = 0; tt < 4; ++tt) sv[ni][tt] = 0.f;
#pragma unroll
        for (int ks = 0; ks < 4; ++ks) {
            const int kb = ks * 8;
#pragma unroll
            for (int ni = 0; ni < 8; ++ni) {
                const int c0 = ni * 8 + g;
                const uint2 k0 = Kp[(kb + tg) * 76 + c0];
                const uint2 k1 = Kp[(kb + tg + 4) * 76 + c0];
                uint32_t bh[2] = { k0.x, k1.x };
                uint32_t bl[2] = { k0.y, k1.y };
                mma16816(sv[ni], qh[ks], bh);
                mma16816(sv[ni], qh[ks], bl);
            }
        }

        // --- mask + scale into exp2 domain ---
        const unsigned long long w0 = g_mbits[mrowbase0 + (m0 >> 6)];
        const unsigned long long w8 = g_mbits[mrowbase8 + (m0 >> 6)];
#pragma unroll
        for (int ni = 0; ni < 8; ++ni) {
            const int cb = ni * 8 + tg * 2;
            sv[ni][0] = ((w0 >> cb) & 1ULL)       ? sv[ni][0] * SCALE2 : -1e9f;
            sv[ni][1] = ((w0 >> (cb + 1)) & 1ULL) ? sv[ni][1] * SCALE2 : -1e9f;
            sv[ni][2] = ((w8 >> cb) & 1ULL)       ? sv[ni][2] * SCALE2 : -1e9f;
            sv[ni][3] = ((w8 >> (cb + 1)) & 1ULL) ? sv[ni][3] * SCALE2 : -1e9f;
        }

        // --- online softmax (exp2 domain) ---
        float mx0 = -INFINITY, mx8 = -INFINITY;
#pragma unroll
        for (int ni = 0; ni < 8; ++ni) {
            mx0 = fmaxf(mx0, fmaxf(sv[ni][0], sv[ni][1]));
            mx8 = fmaxf(mx8, fmaxf(sv[ni][2], sv[ni][3]));
        }
        mx0 = fmaxf(mx0, __shfl_xor_sync(0xffffffffu, mx0, 1));
        mx0 = fmaxf(mx0, __shfl_xor_sync(0xffffffffu, mx0, 2));
        mx8 = fmaxf(mx8, __shfl_xor_sync(0xffffffffu, mx8, 1));
        mx8 = fmaxf(mx8, __shfl_xor_sync(0xffffffffu, mx8, 2));
        const float mn0 = fmaxf(mrow0, mx0), mn8 = fmaxf(mrow8, mx8);
        const float al0 = exp2f(mrow0 - mn0), al8 = exp2f(mrow8 - mn8);
        mrow0 = mn0; mrow8 = mn8;
        float sum0 = 0.f, sum8 = 0.f;
#pragma unroll
        for (int ni = 0; ni < 8; ++ni) {
            sv[ni][0] = exp2f(sv[ni][0] - mn0); sum0 += sv[ni][0];
            sv[ni][1] = exp2f(sv[ni][1] - mn0); sum0 += sv[ni][1];
            sv[ni][2] = exp2f(sv[ni][2] - mn8); sum8 += sv[ni][2];
            sv[ni][3] = exp2f(sv[ni][3] - mn8); sum8 += sv[ni][3];
        }
        sum0 += __shfl_xor_sync(0xffffffffu, sum0, 1);
        sum0 += __shfl_xor_sync(0xffffffffu, sum0, 2);
        sum8 += __shfl_xor_sync(0xffffffffu, sum8, 1);
        sum8 += __shfl_xor_sync(0xffffffffu, sum8, 2);
        lsum0 = lsum0 * al0 + sum0;
        lsum8 = lsum8 * al8 + sum8;
#pragma unroll
        for (int ni = 0; ni < 8; ++ni) {
            oacc[ni][0] *= al0; oacc[ni][1] *= al0;
            oacc[ni][2] *= al8; oacc[ni][3] *= al8;
        }

        // --- pack P ---
        uint32_t ph01[8], pl01[8], ph23[8], pl23[8];
#pragma unroll
        for (int ni = 0; ni < 8; ++ni) {
            const float h0 = bf16val(sv[ni][0]), h1 = bf16val(sv[ni][1]);
            ph01[ni] = pk2(h0, h1);
            pl01[ni] = pk2(sv[ni][0] - h0, sv[ni][1] - h1);
            const float h2 = bf16val(sv[ni][2]), h3 = bf16val(sv[ni][3]);
            ph23[ni] = pk2(h2, h3);
            pl23[ni] = pk2(sv[ni][2] - h2, sv[ni][3] - h3);
        }

        // --- O += P V (3x split) ---
#pragma unroll
        for (int j = 0; j < 4; ++j) {
            const int kb = j * 8;
            uint32_t ah[4]  = { ph01[2 * j], ph23[2 * j], ph01[2 * j + 1], ph23[2 * j + 1] };
            uint32_t alr[4] = { pl01[2 * j], pl23[2 * j], pl01[2 * j + 1], pl23[2 * j + 1] };
#pragma unroll
            for (int ni = 0; ni < 8; ++ni) {
                const int c0 = ni * 8 + g;
                const uint2 v0 = Vp[(kb + tg) * 76 + c0];
                const uint2 v1 = Vp[(kb + tg + 4) * 76 + c0];
                uint32_t bh[2] = { v0.x, v1.x };
                uint32_t bl[2] = { v0.y, v1.y };
                mma16816(oacc[ni], ah, bh);
                mma16816(oacc[ni], ah, bl);
                mma16816(oacc[ni], alr, bh);
            }
        }

        if (t + 1 < NN / 64) {
            AT_STS((t + 1) & 1);
            if (t + 2 < NN / 64) AT_LDG((t + 2) * 64);
        }
        __syncthreads();
    }
#undef AT_LDG
#undef AT_STS

    // --- epilogue: normalize, stage per-warp [64 dk][17], coalesced store ---
    const float inv0 = 1.f / lsum0, inv8 = 1.f / lsum8;
    float* os = (float*)smu2 + warp * (64 * 17);
#pragma unroll
    for (int ni = 0; ni < 8; ++ni) {
        const int dk0 = ni * 8 + tg * 2;
        os[(dk0 + 0) * 17 + g]     = oacc[ni][0] * inv0;
        os[(dk0 + 1) * 17 + g]     = oacc[ni][1] * inv0;
        os[(dk0 + 0) * 17 + 8 + g] = oacc[ni][2] * inv8;
        os[(dk0 + 1) * 17 + 8 + g] = oacc[ni][3] * inv8;
    }
    __syncwarp();
#pragma unroll
    for (int t = 0; t < 2; ++t) {
        const int dk = lane * 2 + t;
        float* dst = g_x + ((size_t)b * DD + (size_t)dk * HH + h) * NN + n0 + rb;
        const float* src = os + dk * 17;
#pragma unroll
        for (int q4 = 0; q4 < 4; ++q4)
            *(float4*)(dst + q4 * 4) =
                make_float4(src[q4 * 4], src[q4 * 4 + 1], src[q4 * 4 + 2], src[q4 * 4 + 3]);
    }
}

// ---------------------------------------------------------------------------
// Launch
// ---------------------------------------------------------------------------
extern "C" void kernel_launch(void* const* d_in, const int* in_sizes, int n_in,
                              void* d_out, int out_size)
{
    const float* init_query = (const float*)d_in[0];
    const float* key_t      = (const float*)d_in[1];
    const float* value      = (const float*)d_in[2];
    const int*   mask       = (const int*)  d_in[3];
    const float* Wq    = (const float*)d_in[4];
    const float* bq    = (const float*)d_in[5];
    const float* Wk    = (const float*)d_in[6];
    const float* bk    = (const float*)d_in[7];
    const float* Wv    = (const float*)d_in[8];
    const float* bv    = (const float*)d_in[9];
    const float* Wm    = (const float*)d_in[10];
    const float* bm    = (const float*)d_in[11];
    const float* W1    = (const float*)d_in[12];
    const float* b1    = (const float*)d_in[13];
    const float* gamma = (const float*)d_in[14];
    const float* beta  = (const float*)d_in[15];
    const float* rmean = (const float*)d_in[16];
    const float* rvar  = (const float*)d_in[17];
    const float* W2    = (const float*)d_in[18];
    const float* b2    = (const float*)d_in[19];
    float* out = (float*)d_out;

    float *p_x, *p_xm, *p_h;
    cudaGetSymbolAddress((void**)&p_x,  g_x);
    cudaGetSymbolAddress((void**)&p_xm, g_xm);
    cudaGetSymbolAddress((void**)&p_h,  g_h);

    cudaFuncSetAttribute(attn_tc_kernel,
                         cudaFuncAttributeMaxDynamicSharedMemorySize, ATT_SMEM);
    cudaFuncSetAttribute(qkv_kernel,
                         cudaFuncAttributeMaxDynamicSharedMemorySize, GEMM_SMEM);
    cudaFuncSetAttribute(gemm_kernel<0>,
                         cudaFuncAttributeMaxDynamicSharedMemorySize, GEMM_SMEM);
    cudaFuncSetAttribute(gemm_kernel<1>,
                         cudaFuncAttributeMaxDynamicSharedMemorySize, GEMM_SMEM);

    // 0) mask -> bitmask
    maskbits_kernel<<<512, 256>>>(mask);
    // 1) q/k/v projections -> packed split-bf16 Q/K/V
    qkv_kernel<<<dim3(16, 4, 6), 256, GEMM_SMEM>>>(init_query, key_t, value,
                                                   Wq, bq, Wk, bk, Wv, bv);
    // 2) flash attention -> g_x (fp32)
    attn_tc_kernel<<<dim3(NN / 64, HH, BB), 128, ATT_SMEM>>>();
    // 3) merge conv
    gemm_kernel<0><<<dim3(16, 4, BB), 256, GEMM_SMEM>>>(Wm, p_x, nullptr, bm,
                                                        nullptr, nullptr, nullptr, nullptr,
                                                        p_xm, DD, DD);
    // 4) W1 @ [xm ; init_query] + BN + ReLU
    gemm_kernel<1><<<dim3(16, 8, BB), 256, GEMM_SMEM>>>(W1, p_xm, init_query, b1,
                                                        rmean, rvar, gamma, beta,
                                                        p_h, DD2, DD2);
    // 5) out = W2 @ h + b2
    gemm_kernel<0><<<dim3(16, 4, BB), 256, GEMM_SMEM>>>(W2, p_h, nullptr, b2,
                                                        nullptr, nullptr, nullptr, nullptr,
                                                        out, DD, DD2);
}